// round 1
// baseline (speedup 1.0000x reference)
#include <cuda_runtime.h>

// ---------------------------------------------------------------------------
// DNN_KalmanNet_SLAM: fused single-kernel implementation.
// x(14) -> ReLU(W1 x + b1)(560) -> GRUCell0(->145) -> GRUCell1(->145)
//       -> ReLU(W2a h + b2a)(40) -> W2b(.)+b2b -> out(10)
// One persistent grid with software grid barriers (graph-capturable,
// allocation-free, deterministic across replays: generation counter is
// monotone, arrival counter returns to 0 after every barrier).
// ---------------------------------------------------------------------------

#define NBLOCKS  40
#define NTHREADS 256
#define NWARPS   ((NBLOCKS * NTHREADS) / 32)   // 320

#define H1   560
#define GH   145        // GRU hidden
#define G3   435        // 3*GH

// Intermediates (device globals: no allocation allowed)
__device__ float g_l1[H1];
__device__ float g_gh[2 * G3];   // [0,435): Whh0@hn0+bhh0 ; [435,870): layer 1
__device__ float g_h0[GH];
__device__ float g_h1[GH];

// Grid barrier state
__device__ unsigned g_bar_count = 0;
__device__ unsigned g_bar_gen   = 0;

__device__ __forceinline__ float wsum(float v) {
#pragma unroll
    for (int o = 16; o; o >>= 1) v += __shfl_down_sync(0xffffffffu, v, o);
    return v;
}

__device__ __forceinline__ void grid_barrier() {
    __threadfence();          // make this thread's prior writes visible (L2)
    __syncthreads();          // all block threads' writes done before arrive
    if (threadIdx.x == 0) {
        volatile unsigned* gp = &g_bar_gen;
        unsigned my = *gp;
        if (atomicAdd(&g_bar_count, 1u) == NBLOCKS - 1u) {
            g_bar_count = 0;        // safe: everyone has arrived
            __threadfence();
            atomicAdd(&g_bar_gen, 1u);   // release
        } else {
            while (*gp == my) { }        // spin (blocks are co-resident)
        }
    }
    __syncthreads();
    __threadfence();          // acquire-ish: order subsequent loads
}

__device__ __forceinline__ float sigmoidf_(float x) {
    return 1.0f / (1.0f + __expf(-x));
}

__global__ __launch_bounds__(NTHREADS, 1)
void kalmannet_kernel(
    const float* __restrict__ state_inno, const float* __restrict__ obs_inno,
    const float* __restrict__ diff_state, const float* __restrict__ diff_obs,
    const float* __restrict__ W1,  const float* __restrict__ b1,
    const float* __restrict__ Wih0, const float* __restrict__ Whh0,
    const float* __restrict__ bih0, const float* __restrict__ bhh0,
    const float* __restrict__ Wih1, const float* __restrict__ Whh1,
    const float* __restrict__ bih1, const float* __restrict__ bhh1,
    const float* __restrict__ W2a, const float* __restrict__ b2a,
    const float* __restrict__ W2b, const float* __restrict__ b2b,
    const float* __restrict__ hn,
    float* __restrict__ out)
{
    const int tid  = blockIdx.x * NTHREADS + threadIdx.x;
    const int wid  = tid >> 5;          // global warp id
    const int lane = threadIdx.x & 31;
    const int lw   = threadIdx.x >> 5;  // local warp id

    __shared__ float s_x[14];
    __shared__ float s_l1[H1];
    __shared__ float s_v[GH];
    __shared__ float s_hid[40];

    // load concatenated input vector
    if (threadIdx.x < 14) {
        int i = threadIdx.x;
        float v;
        if      (i < 5)  v = state_inno[i];
        else if (i < 7)  v = obs_inno[i - 5];
        else if (i < 12) v = diff_state[i - 7];
        else             v = diff_obs[i - 12];
        s_x[i] = v;
    }
    __syncthreads();

    // ---------------- Stage A (independent work) ----------------
    // l1_out = relu(W1 @ x + b1): thread-per-row (14-dot)
    for (int r = tid; r < H1; r += NBLOCKS * NTHREADS) {
        const float* wr = W1 + r * 14;
        float s = b1[r];
#pragma unroll
        for (int k = 0; k < 14; k++) s = fmaf(wr[k], s_x[k], s);
        g_l1[r] = fmaxf(s, 0.0f);
    }
    // gh{0,1} = Whh{0,1} @ hn{0,1} + bhh{0,1}: warp-per-row (145-dot)
    for (int i = wid; i < 2 * G3; i += NWARPS) {
        const int layer = (i >= G3);
        const int r = i - layer * G3;
        const float* W = layer ? Whh1 : Whh0;
        const float* b = layer ? bhh1 : bhh0;
        const float* h = hn + layer * GH;
        const float* wr = W + r * GH;
        float s = 0.0f;
        for (int k = lane; k < GH; k += 32) s = fmaf(wr[k], __ldg(h + k), s);
        s = wsum(s);
        if (lane == 0) g_gh[i] = s + b[r];
    }

    grid_barrier();   // l1_out, gh0 ready

    // ---------------- Stage B: GRU layer 0 ----------------
    for (int i = threadIdx.x; i < H1; i += NTHREADS) s_l1[i] = g_l1[i];
    __syncthreads();

    // warp e computes rows e, e+145, e+290 of Wih0 @ l1 (so the GRU
    // elementwise update needs no extra barrier)
    for (int e = wid; e < GH; e += NWARPS) {
        const float* w0 = Wih0 + e * H1;
        float sr = 0.f, sz = 0.f, sn = 0.f;
        for (int k = lane; k < H1; k += 32) {
            float xv = s_l1[k];
            sr = fmaf(w0[k],            xv, sr);
            sz = fmaf(w0[145 * H1 + k], xv, sz);
            sn = fmaf(w0[290 * H1 + k], xv, sn);
        }
        sr = wsum(sr); sz = wsum(sz); sn = wsum(sn);
        if (lane == 0) {
            float r  = sigmoidf_(sr + bih0[e]       + g_gh[e]);
            float z  = sigmoidf_(sz + bih0[e + 145] + g_gh[e + 145]);
            float n  = tanhf(sn + bih0[e + 290] + r * g_gh[e + 290]);
            g_h0[e] = (1.0f - z) * n + z * __ldg(hn + e);
        }
    }

    grid_barrier();   // h0 ready (gh1 done since stage A)

    // ---------------- Stage C: GRU layer 1 ----------------
    for (int i = threadIdx.x; i < GH; i += NTHREADS) s_v[i] = g_h0[i];
    __syncthreads();

    for (int e = wid; e < GH; e += NWARPS) {
        const float* w1 = Wih1 + e * GH;
        float sr = 0.f, sz = 0.f, sn = 0.f;
        for (int k = lane; k < GH; k += 32) {
            float xv = s_v[k];
            sr = fmaf(w1[k],            xv, sr);
            sz = fmaf(w1[145 * GH + k], xv, sz);
            sn = fmaf(w1[290 * GH + k], xv, sn);
        }
        sr = wsum(sr); sz = wsum(sz); sn = wsum(sn);
        if (lane == 0) {
            float r  = sigmoidf_(sr + bih1[e]       + g_gh[G3 + e]);
            float z  = sigmoidf_(sz + bih1[e + 145] + g_gh[G3 + e + 145]);
            float n  = tanhf(sn + bih1[e + 290] + r * g_gh[G3 + e + 290]);
            g_h1[e] = (1.0f - z) * n + z * __ldg(hn + GH + e);
        }
    }

    grid_barrier();   // h1 ready

    // ---------------- Stage D: output head (block 0 only) ----------------
    if (blockIdx.x == 0) {
        for (int i = threadIdx.x; i < GH; i += NTHREADS) s_v[i] = g_h1[i];
        __syncthreads();
        for (int r = lw; r < 40; r += (NTHREADS / 32)) {
            const float* wr = W2a + r * GH;
            float s = 0.0f;
            for (int k = lane; k < GH; k += 32) s = fmaf(wr[k], s_v[k], s);
            s = wsum(s);
            if (lane == 0) s_hid[r] = fmaxf(s + b2a[r], 0.0f);
        }
        __syncthreads();
        if (threadIdx.x < 10) {
            const float* wr = W2b + threadIdx.x * 40;
            float s = b2b[threadIdx.x];
#pragma unroll
            for (int k = 0; k < 40; k++) s = fmaf(wr[k], s_hid[k], s);
            out[threadIdx.x] = s;
        }
    }
}

extern "C" void kernel_launch(void* const* d_in, const int* in_sizes, int n_in,
                              void* d_out, int out_size) {
    (void)in_sizes; (void)n_in; (void)out_size;
    kalmannet_kernel<<<NBLOCKS, NTHREADS>>>(
        (const float*)d_in[0],  (const float*)d_in[1],
        (const float*)d_in[2],  (const float*)d_in[3],
        (const float*)d_in[4],  (const float*)d_in[5],
        (const float*)d_in[6],  (const float*)d_in[7],
        (const float*)d_in[8],  (const float*)d_in[9],
        (const float*)d_in[10], (const float*)d_in[11],
        (const float*)d_in[12], (const float*)d_in[13],
        (const float*)d_in[14], (const float*)d_in[15],
        (const float*)d_in[16], (const float*)d_in[17],
        (const float*)d_in[18],
        (float*)d_out);
}

// round 3
// speedup vs baseline: 1.3232x; 1.3232x over previous
#include <cuda_runtime.h>

// ---------------------------------------------------------------------------
// DNN_KalmanNet_SLAM — fused, latency-optimized.
//  x(14) -> ReLU(W1 x+b1)(560) -> GRU0(->145) -> GRU1(->145)
//        -> ReLU(W2a h+b2a)(40) -> W2b+b2b -> out(10)
//
// 19 blocks x 256 threads = 152 warps. Warp e owns GRU element e for BOTH
// layers: recurrent dots (Whh vs hn) computed up-front (independent),
// layer-1 recurrent result carried in registers across grid barrier 1.
// l1 recomputed redundantly per block (cheap) -> only 2 grid barriers.
// Head block's idle warps prefetch W2a into smem during stage 1.
// ---------------------------------------------------------------------------

#define NB     19
#define NT     256
#define WPB    8
#define H1     560
#define GH     145
#define HEADB  (NB - 1)

__device__ float    g_h0[GH];
__device__ float    g_h1[GH];
__device__ unsigned g_cnt = 0;
__device__ unsigned g_gen = 0;

__device__ __forceinline__ float wsum(float v) {
#pragma unroll
    for (int o = 16; o; o >>= 1) v += __shfl_down_sync(0xffffffffu, v, o);
    return v;
}
__device__ __forceinline__ float sigm(float x) { return 1.0f / (1.0f + __expf(-x)); }
__device__ __forceinline__ float tanha(float x) {
    float y; asm("tanh.approx.f32 %0, %1;" : "=f"(y) : "f"(x)); return y;
}

__device__ __forceinline__ void gbar() {
    __threadfence();
    __syncthreads();
    if (threadIdx.x == 0) {
        volatile unsigned* gp = &g_gen;
        unsigned my = *gp;
        if (atomicAdd(&g_cnt, 1u) == NB - 1u) {
            g_cnt = 0;
            __threadfence();
            atomicAdd(&g_gen, 1u);
        } else {
            while (*gp == my) { __nanosleep(32); }
        }
    }
    __syncthreads();
    __threadfence();
}

__global__ __launch_bounds__(NT, 1)
void kalmannet_kernel(
    const float* __restrict__ state_inno, const float* __restrict__ obs_inno,
    const float* __restrict__ diff_state, const float* __restrict__ diff_obs,
    const float* __restrict__ W1,   const float* __restrict__ b1,
    const float* __restrict__ Wih0, const float* __restrict__ Whh0,
    const float* __restrict__ bih0, const float* __restrict__ bhh0,
    const float* __restrict__ Wih1, const float* __restrict__ Whh1,
    const float* __restrict__ bih1, const float* __restrict__ bhh1,
    const float* __restrict__ W2a,  const float* __restrict__ b2a,
    const float* __restrict__ W2b,  const float* __restrict__ b2b,
    const float* __restrict__ hn,
    float* __restrict__ out)
{
    __shared__ __align__(16) float s_l1[H1];
    __shared__ float s_x[16];
    __shared__ float s_hn[2 * GH];
    __shared__ float s_v[GH];
    __shared__ float s_hid[40];
    __shared__ float s_w2a[40 * GH];   // head block only

    const int t    = threadIdx.x;
    const int lane = t & 31;
    const int lw   = t >> 5;
    const int e    = blockIdx.x * WPB + lw;
    const bool act = (e < GH);

    // ---- inputs ----
    if (t < 14) {
        float v;
        if      (t < 5)  v = state_inno[t];
        else if (t < 7)  v = obs_inno[t - 5];
        else if (t < 12) v = diff_state[t - 7];
        else             v = diff_obs[t - 12];
        s_x[t] = v;
    }
    for (int i = t; i < 2 * GH; i += NT) s_hn[i] = __ldg(hn + i);
    __syncthreads();

    // ---- l1 (redundant per block, cheap) ----
    for (int r = t; r < H1; r += NT) {
        const float* w = W1 + r * 14;
        float s = b1[r];
#pragma unroll
        for (int k = 0; k < 14; k++) s = fmaf(w[k], s_x[k], s);
        s_l1[r] = fmaxf(s, 0.0f);
    }

    // ---- head-block idle warps prefetch W2a into smem ----
    if (blockIdx.x == HEADB && lw >= 1) {
        for (int i = t - 32; i < 40 * GH; i += NT - 32) s_w2a[i] = W2a[i];
    }

    // ---- recurrent dots for BOTH layers (independent of l1) ----
    float A0 = 0.f, A1 = 0.f, A2 = 0.f;   // layer0 r,z,n
    float B0 = 0.f, B1 = 0.f, B2 = 0.f;   // layer1 r,z,n (register-carried)
    float bi0r = 0.f, bi0z = 0.f, bi0n = 0.f;
    float bi1r = 0.f, bi1z = 0.f, bi1n = 0.f;
    if (act) {
        const float* w0r = Whh0 + e * GH;
        const float* w0z = Whh0 + (e + GH) * GH;
        const float* w0n = Whh0 + (e + 2 * GH) * GH;
        const float* w1r = Whh1 + e * GH;
        const float* w1z = Whh1 + (e + GH) * GH;
        const float* w1n = Whh1 + (e + 2 * GH) * GH;
#pragma unroll 5
        for (int k = lane; k < GH; k += 32) {
            float h0v = s_hn[k], h1v = s_hn[GH + k];
            A0 = fmaf(w0r[k], h0v, A0);
            A1 = fmaf(w0z[k], h0v, A1);
            A2 = fmaf(w0n[k], h0v, A2);
            B0 = fmaf(w1r[k], h1v, B0);
            B1 = fmaf(w1z[k], h1v, B1);
            B2 = fmaf(w1n[k], h1v, B2);
        }
        A0 = wsum(A0); A1 = wsum(A1); A2 = wsum(A2);
        B0 = wsum(B0); B1 = wsum(B1); B2 = wsum(B2);
        if (lane == 0) {
            A0 += bhh0[e];  A1 += bhh0[e + GH];  A2 += bhh0[e + 2 * GH];
            B0 += bhh1[e];  B1 += bhh1[e + GH];  B2 += bhh1[e + 2 * GH];
            bi0r = bih0[e]; bi0z = bih0[e + GH]; bi0n = bih0[e + 2 * GH];
            bi1r = bih1[e]; bi1z = bih1[e + GH]; bi1n = bih1[e + 2 * GH];
        }
    }
    __syncthreads();   // s_l1 ready

    // ---- GRU layer 0: Wih0 @ l1 with float4 loads ----
    if (act) {
        const float4* xr = (const float4*)s_l1;
        const float4* wr = (const float4*)(Wih0 + e * H1);
        const float4* wz = (const float4*)(Wih0 + (e + GH) * H1);
        const float4* wn = (const float4*)(Wih0 + (e + 2 * GH) * H1);
        float sr = 0.f, sz = 0.f, sn = 0.f;
#pragma unroll
        for (int i = 0; i < 5; i++) {
            int k = lane + 32 * i;
            if (k < H1 / 4) {
                float4 x = xr[k];
                float4 a = wr[k];
                sr += a.x * x.x + a.y * x.y + a.z * x.z + a.w * x.w;
                float4 b = wz[k];
                sz += b.x * x.x + b.y * x.y + b.z * x.z + b.w * x.w;
                float4 c = wn[k];
                sn += c.x * x.x + c.y * x.y + c.z * x.z + c.w * x.w;
            }
        }
        sr = wsum(sr); sz = wsum(sz); sn = wsum(sn);
        if (lane == 0) {
            float r = sigm(sr + bi0r + A0);
            float z = sigm(sz + bi0z + A1);
            float n = tanha(sn + bi0n + r * A2);
            g_h0[e] = (1.0f - z) * n + z * s_hn[e];
        }
    }

    gbar();   // h0 visible

    // ---- GRU layer 1: Wih1 @ h0 ----
    for (int i = t; i < GH; i += NT) s_v[i] = g_h0[i];
    __syncthreads();
    if (act) {
        const float* wr = Wih1 + e * GH;
        const float* wz = Wih1 + (e + GH) * GH;
        const float* wn = Wih1 + (e + 2 * GH) * GH;
        float sr = 0.f, sz = 0.f, sn = 0.f;
#pragma unroll 5
        for (int k = lane; k < GH; k += 32) {
            float x = s_v[k];
            sr = fmaf(wr[k], x, sr);
            sz = fmaf(wz[k], x, sz);
            sn = fmaf(wn[k], x, sn);
        }
        sr = wsum(sr); sz = wsum(sz); sn = wsum(sn);
        if (lane == 0) {
            float r = sigm(sr + bi1r + B0);
            float z = sigm(sz + bi1z + B1);
            float n = tanha(sn + bi1n + r * B2);
            g_h1[e] = (1.0f - z) * n + z * s_hn[GH + e];
        }
    }

    gbar();   // h1 visible

    // ---- output head (last block; W2a already in smem) ----
    if (blockIdx.x == HEADB) {
        for (int i = t; i < GH; i += NT) s_v[i] = g_h1[i];
        __syncthreads();
        for (int r = lw; r < 40; r += WPB) {
            const float* w = &s_w2a[r * GH];
            float s = 0.f;
#pragma unroll 5
            for (int k = lane; k < GH; k += 32) s = fmaf(w[k], s_v[k], s);
            s = wsum(s);
            if (lane == 0) s_hid[r] = fmaxf(s + b2a[r], 0.0f);
        }
        __syncthreads();
        if (t < 10) {
            const float* w = W2b + t * 40;
            float s = b2b[t];
#pragma unroll
            for (int k = 0; k < 40; k++) s = fmaf(w[k], s_hid[k], s);
            out[t] = s;
        }
    }
}

extern "C" void kernel_launch(void* const* d_in, const int* in_sizes, int n_in,
                              void* d_out, int out_size) {
    (void)in_sizes; (void)n_in; (void)out_size;
    kalmannet_kernel<<<NB, NT>>>(
        (const float*)d_in[0],  (const float*)d_in[1],
        (const float*)d_in[2],  (const float*)d_in[3],
        (const float*)d_in[4],  (const float*)d_in[5],
        (const float*)d_in[6],  (const float*)d_in[7],
        (const float*)d_in[8],  (const float*)d_in[9],
        (const float*)d_in[10], (const float*)d_in[11],
        (const float*)d_in[12], (const float*)d_in[13],
        (const float*)d_in[14], (const float*)d_in[15],
        (const float*)d_in[16], (const float*)d_in[17],
        (const float*)d_in[18],
        (float*)d_out);
}

// round 9
// speedup vs baseline: 1.4811x; 1.1193x over previous
#include <cuda_runtime.h>

// ---------------------------------------------------------------------------
// DNN_KalmanNet_SLAM — fused, latency-optimized, weight-hoisted.
//  x(14) -> ReLU(W1 x+b1)(560) -> GRU0(->145) -> GRU1(->145)
//        -> ReLU(W2a h+b2a)(40) -> W2b+b2b -> out(10)
//
// 19 blocks x 256 threads = 152 warps; warp e owns GRU element e for BOTH
// layers. All weights whose values are needed AFTER a grid barrier are
// prefetched BEFORE it: Whh dots computed up-front, Wih1 rows held in
// registers, head weights staged to smem by the head block's idle warps.
// Post-barrier critical path = one coalesced L2 read of the hidden vector
// + register FMAs + warp reduction. 2 grid barriers total.
// ---------------------------------------------------------------------------

#define NB     19
#define NT     256
#define WPB    8
#define H1     560
#define GH     145
#define HEADB  (NB - 1)

__device__ float    g_h0[GH];
__device__ float    g_h1[GH];
__device__ unsigned g_cnt = 0;
__device__ unsigned g_gen = 0;

__device__ __forceinline__ float wsum(float v) {
#pragma unroll
    for (int o = 16; o; o >>= 1) v += __shfl_down_sync(0xffffffffu, v, o);
    return v;
}
__device__ __forceinline__ float sigm(float x) { return 1.0f / (1.0f + __expf(-x)); }
__device__ __forceinline__ float tanha(float x) {
    float y; asm("tanh.approx.f32 %0, %1;" : "=f"(y) : "f"(x)); return y;
}

__device__ __forceinline__ void gbar() {
    __threadfence();
    __syncthreads();
    if (threadIdx.x == 0) {
        volatile unsigned* gp = &g_gen;
        unsigned my = *gp;
        if (atomicAdd(&g_cnt, 1u) == NB - 1u) {
            g_cnt = 0;
            __threadfence();
            atomicAdd(&g_gen, 1u);
        } else {
            while (*gp == my) { }
        }
    }
    __syncthreads();
    __threadfence();
}

__global__ __launch_bounds__(NT, 1)
void kalmannet_kernel(
    const float* __restrict__ state_inno, const float* __restrict__ obs_inno,
    const float* __restrict__ diff_state, const float* __restrict__ diff_obs,
    const float* __restrict__ W1,   const float* __restrict__ b1,
    const float* __restrict__ Wih0, const float* __restrict__ Whh0,
    const float* __restrict__ bih0, const float* __restrict__ bhh0,
    const float* __restrict__ Wih1, const float* __restrict__ Whh1,
    const float* __restrict__ bih1, const float* __restrict__ bhh1,
    const float* __restrict__ W2a,  const float* __restrict__ b2a,
    const float* __restrict__ W2b,  const float* __restrict__ b2b,
    const float* __restrict__ hn,
    float* __restrict__ out)
{
    __shared__ __align__(16) float s_l1[H1];
    __shared__ float s_x[16];
    __shared__ float s_hn[2 * GH];
    __shared__ float s_v[GH + 8];
    __shared__ float s_hid[40];
    __shared__ float s_w2a[40 * GH];    // head block only
    __shared__ float s_w2b[10 * 40];    // head block only
    __shared__ float s_b2a[40];
    __shared__ float s_b2b[10];

    const int t    = threadIdx.x;
    const int lane = t & 31;
    const int lw   = t >> 5;
    const int e    = blockIdx.x * WPB + lw;
    const bool act = (e < GH);

    // ---- inputs ----
    if (t < 14) {
        float v;
        if      (t < 5)  v = state_inno[t];
        else if (t < 7)  v = obs_inno[t - 5];
        else if (t < 12) v = diff_state[t - 7];
        else             v = diff_obs[t - 12];
        s_x[t] = v;
    }
    for (int i = t; i < 2 * GH; i += NT) s_hn[i] = __ldg(hn + i);
    __syncthreads();

    // ---- l1 (redundant per block, cheap) ----
    for (int r = t; r < H1; r += NT) {
        const float* w = W1 + r * 14;
        float s = b1[r];
#pragma unroll
        for (int k = 0; k < 14; k++) s = fmaf(w[k], s_x[k], s);
        s_l1[r] = fmaxf(s, 0.0f);
    }

    // ---- head block: idle warps prefetch ALL head weights into smem ----
    if (blockIdx.x == HEADB && lw >= 1) {
        for (int i = t - 32; i < 40 * GH; i += NT - 32) s_w2a[i] = W2a[i];
        if (lw == 1) {
            if (lane < 10) s_b2b[lane] = b2b[lane];
            for (int i = lane; i < 40; i += 32) s_b2a[i] = b2a[i];
        }
        if (lw >= 2) {
            for (int i = t - 64; i < 400; i += NT - 64) s_w2b[i] = W2b[i];
        }
    }

    // ---- prefetch Wih1 rows into registers (independent of h0!) ----
    float w1r[5], w1z[5], w1n[5];
    if (act) {
        const float* pr = Wih1 + e * GH;
        const float* pz = Wih1 + (e + GH) * GH;
        const float* pn = Wih1 + (e + 2 * GH) * GH;
#pragma unroll
        for (int i = 0; i < 5; i++) {
            int k = lane + 32 * i;
            bool ok = (k < GH);
            w1r[i] = ok ? __ldg(pr + k) : 0.f;
            w1z[i] = ok ? __ldg(pz + k) : 0.f;
            w1n[i] = ok ? __ldg(pn + k) : 0.f;
        }
    }

    // ---- recurrent dots for BOTH layers (independent of l1/h0) ----
    float A0 = 0.f, A1 = 0.f, A2 = 0.f;
    float B0 = 0.f, B1 = 0.f, B2 = 0.f;
    float bi0r = 0.f, bi0z = 0.f, bi0n = 0.f;
    float bi1r = 0.f, bi1z = 0.f, bi1n = 0.f;
    if (act) {
        const float* q0r = Whh0 + e * GH;
        const float* q0z = Whh0 + (e + GH) * GH;
        const float* q0n = Whh0 + (e + 2 * GH) * GH;
        const float* q1r = Whh1 + e * GH;
        const float* q1z = Whh1 + (e + GH) * GH;
        const float* q1n = Whh1 + (e + 2 * GH) * GH;
#pragma unroll 5
        for (int k = lane; k < GH; k += 32) {
            float h0v = s_hn[k], h1v = s_hn[GH + k];
            A0 = fmaf(q0r[k], h0v, A0);
            A1 = fmaf(q0z[k], h0v, A1);
            A2 = fmaf(q0n[k], h0v, A2);
            B0 = fmaf(q1r[k], h1v, B0);
            B1 = fmaf(q1z[k], h1v, B1);
            B2 = fmaf(q1n[k], h1v, B2);
        }
        A0 = wsum(A0); A1 = wsum(A1); A2 = wsum(A2);
        B0 = wsum(B0); B1 = wsum(B1); B2 = wsum(B2);
        if (lane == 0) {
            A0 += bhh0[e];  A1 += bhh0[e + GH];  A2 += bhh0[e + 2 * GH];
            B0 += bhh1[e];  B1 += bhh1[e + GH];  B2 += bhh1[e + 2 * GH];
            bi0r = bih0[e]; bi0z = bih0[e + GH]; bi0n = bih0[e + 2 * GH];
            bi1r = bih1[e]; bi1z = bih1[e + GH]; bi1n = bih1[e + 2 * GH];
        }
    }
    __syncthreads();   // s_l1 ready

    // ---- GRU layer 0: Wih0 @ l1, float4 loads ----
    if (act) {
        const float4* xr = (const float4*)s_l1;
        const float4* wr = (const float4*)(Wih0 + e * H1);
        const float4* wz = (const float4*)(Wih0 + (e + GH) * H1);
        const float4* wn = (const float4*)(Wih0 + (e + 2 * GH) * H1);
        float sr = 0.f, sz = 0.f, sn = 0.f;
#pragma unroll
        for (int i = 0; i < 5; i++) {
            int k = lane + 32 * i;
            if (k < H1 / 4) {
                float4 x = xr[k];
                float4 a = wr[k];
                sr += a.x * x.x + a.y * x.y + a.z * x.z + a.w * x.w;
                float4 b = wz[k];
                sz += b.x * x.x + b.y * x.y + b.z * x.z + b.w * x.w;
                float4 c = wn[k];
                sn += c.x * x.x + c.y * x.y + c.z * x.z + c.w * x.w;
            }
        }
        sr = wsum(sr); sz = wsum(sz); sn = wsum(sn);
        if (lane == 0) {
            float r = sigm(sr + bi0r + A0);
            float z = sigm(sz + bi0z + A1);
            float n = tanha(sn + bi0n + r * A2);
            g_h0[e] = (1.0f - z) * n + z * s_hn[e];
        }
    }

    gbar();   // h0 visible

    // ---- GRU layer 1: register weights x g_h0 (direct L2 read) ----
    if (act) {
        float sr = 0.f, sz = 0.f, sn = 0.f;
#pragma unroll
        for (int i = 0; i < 5; i++) {
            int k = lane + 32 * i;
            float x = (k < GH) ? g_h0[k] : 0.f;
            sr = fmaf(w1r[i], x, sr);
            sz = fmaf(w1z[i], x, sz);
            sn = fmaf(w1n[i], x, sn);
        }
        sr = wsum(sr); sz = wsum(sz); sn = wsum(sn);
        if (lane == 0) {
            float r = sigm(sr + bi1r + B0);
            float z = sigm(sz + bi1z + B1);
            float n = tanha(sn + bi1n + r * B2);
            g_h1[e] = (1.0f - z) * n + z * s_hn[GH + e];
        }
    }

    gbar();   // h1 visible

    // ---- output head (head block; all weights already in smem) ----
    if (blockIdx.x == HEADB) {
        for (int i = t; i < GH; i += NT) s_v[i] = g_h1[i];
        __syncthreads();
        for (int r = lw; r < 40; r += WPB) {
            const float* w = &s_w2a[r * GH];
            float s = 0.f;
#pragma unroll 5
            for (int k = lane; k < GH; k += 32) s = fmaf(w[k], s_v[k], s);
            s = wsum(s);
            if (lane == 0) s_hid[r] = fmaxf(s + s_b2a[r], 0.0f);
        }
        __syncthreads();
        if (t < 10) {
            const float* w = &s_w2b[t * 40];
            float s = s_b2b[t];
#pragma unroll
            for (int k = 0; k < 40; k++) s = fmaf(w[k], s_hid[k], s);
            out[t] = s;
        }
    }
}

extern "C" void kernel_launch(void* const* d_in, const int* in_sizes, int n_in,
                              void* d_out, int out_size) {
    (void)in_sizes; (void)n_in; (void)out_size;
    kalmannet_kernel<<<NB, NT>>>(
        (const float*)d_in[0],  (const float*)d_in[1],
        (const float*)d_in[2],  (const float*)d_in[3],
        (const float*)d_in[4],  (const float*)d_in[5],
        (const float*)d_in[6],  (const float*)d_in[7],
        (const float*)d_in[8],  (const float*)d_in[9],
        (const float*)d_in[10], (const float*)d_in[11],
        (const float*)d_in[12], (const float*)d_in[13],
        (const float*)d_in[14], (const float*)d_in[15],
        (const float*)d_in[16], (const float*)d_in[17],
        (const float*)d_in[18],
        (float*)d_out);
}